// round 14
// baseline (speedup 1.0000x reference)
#include <cuda_runtime.h>
#include <cuda_fp16.h>
#include <cstdint>
#include <cstddef>

// Problem constants
#define SEQ   2048
#define BATCH 16
#define HID   512
#define OUT_F 10
#define NLAY  5
#define MROWS (SEQ * BATCH)      // 32768
#define NCOLS (3 * HID)          // 1536
#define BH    (BATCH * HID)      // 8192
#define BH2   (BH / 2)           // 4096

// Scan chunking (64 chunks x 32 steps: single-wave wide grid)
#define NCH   64
#define CHL   (SEQ / NCH)        // 32 timesteps per chunk
#define SUNROLL 8

// ---------------- device scratch (no allocations allowed) ----------------
__device__ __half g_U [(size_t)MROWS * NCOLS];         // 96 MB: [xt | f | r] fp16
__device__ __half g_A0[(size_t)MROWS * HID];           // 32 MB activations ping
__device__ __half g_A1[(size_t)MROWS * HID];           // 32 MB activations pong
__device__ __half g_Wh[(size_t)NLAY * NCOLS * HID];    // 7.5 MB weights fp16
__device__ float g_P  [(size_t)NCH * BH];              // 2 MB chunk f-products
__device__ float g_S  [(size_t)NCH * BH];              // 2 MB chunk end-states

// ================= arch-neutral PTX helpers (sm_80+ features only) =======
__device__ __forceinline__ uint32_t smem_to_u32(const void* p) {
    uint32_t a;
    asm("{ .reg .u64 t; cvta.to.shared.u64 t, %1; cvt.u32.u64 %0, t; }"
        : "=r"(a) : "l"(p));
    return a;
}
__device__ __forceinline__ void cp16(uint32_t saddr, const void* g) {
    asm volatile("cp.async.cg.shared.global [%0], [%1], 16;"
                 :: "r"(saddr), "l"(g) : "memory");
}
__device__ __forceinline__ void cp_commit() {
    asm volatile("cp.async.commit_group;" ::: "memory");
}
template <int N>
__device__ __forceinline__ void cp_wait() {
    asm volatile("cp.async.wait_group %0;" :: "n"(N) : "memory");
}
__device__ __forceinline__ void ldsm_x4(uint32_t (&r)[4], uint32_t addr) {
    asm volatile("ldmatrix.sync.aligned.m8n8.x4.shared.b16 {%0,%1,%2,%3}, [%4];"
                 : "=r"(r[0]), "=r"(r[1]), "=r"(r[2]), "=r"(r[3])
                 : "r"(addr));
}
__device__ __forceinline__ void mma_fp16(float (&d)[4], const uint32_t (&a)[4],
                                         uint32_t b0, uint32_t b1) {
    asm volatile(
        "mma.sync.aligned.m16n8k16.row.col.f32.f16.f16.f32 "
        "{%0,%1,%2,%3}, {%4,%5,%6,%7}, {%8,%9}, {%0,%1,%2,%3};"
        : "+f"(d[0]), "+f"(d[1]), "+f"(d[2]), "+f"(d[3])
        : "r"(a[0]), "r"(a[1]), "r"(a[2]), "r"(a[3]), "r"(b0), "r"(b1));
}

// ============================================================
// fp32 -> fp16 convert.  n4 = element_count / 4.
// ============================================================
__global__ void convert_fp16(const float* __restrict__ in,
                             __half* __restrict__ out, int n4) {
    int i = blockIdx.x * blockDim.x + threadIdx.x;
    if (i >= n4) return;
    float4 v = reinterpret_cast<const float4*>(in)[i];
    __half h[4];
    h[0] = __float2half_rn(v.x);  h[1] = __float2half_rn(v.y);
    h[2] = __float2half_rn(v.z);  h[3] = __float2half_rn(v.w);
    reinterpret_cast<uint2*>(out)[i] = *reinterpret_cast<uint2*>(h);
}

// ============================================================
// Persistent tensor-core GEMM via mma.sync (fp16, fp32 accum):
//   U[M=32768, N=1536] = A[M,512] * W[N,512]^T   (U stored fp16)
// Grid = GPERS persistent CTAs; cross-tile cp.async ring, one sync/stage.
// CTA tile 128(M) x 256(N), BK=64, 16 warps (4x4), warp tile 32x64.
// Epilogue: cols >= 512 -> sigmoid(u + bias[n-512]); half2 stores.
// (At ~92% of the sm_100 legacy HMMA ceiling — unchanged, protected.)
// ============================================================
#define BK 64
#define PITCH_B 144
#define A_TILE_B (128 * PITCH_B)          // 18432 B
#define B_TILE_B (256 * PITCH_B)          // 36864 B
#define STAGE_B (A_TILE_B + B_TILE_B)     // 55296 B
#define NSTAGE 3
#define SMEM_GEMM (NSTAGE * STAGE_B)      // 165888 B
#define NTILE_N 6                         // 1536 / 256
#define NTILE   (NTILE_N * (MROWS / 128)) // 1536 tiles
#define KST     8                         // K-stages per tile (512/64)
#define GPERS   148                       // persistent CTAs

__device__ __forceinline__ void issue_stage_g(
    uint32_t sb, const __half* __restrict__ Ah,
    const __half* __restrict__ Wh,
    int bid, int g, int tid)
{
    const int i    = g >> 3;
    const int s    = g & 7;
    const int tile = bid + i * GPERS;
    const int bn   = (tile % NTILE_N) * 256;
    const int bm   = (tile / NTILE_N) * 128;
    const int k0   = s * BK;
    const uint32_t sbase = sb + (uint32_t)(g % NSTAGE) * STAGE_B;
#pragma unroll
    for (int q = 0; q < 6; q++) {
        int c = tid + q * 512;
        const __half* src;
        uint32_t toff;
        int row, kc;
        if (q < 2) {                       // A: 128 rows
            row = c >> 3;  kc = c & 7;
            src  = Ah + (size_t)(bm + row) * HID + k0 + kc * 8;
            toff = 0u;
        } else {                           // W: 256 rows
            int idx = c - 1024;
            row = idx >> 3;  kc = idx & 7;
            src  = Wh + (size_t)(bn + row) * HID + k0 + kc * 8;
            toff = (uint32_t)A_TILE_B;
        }
        cp16(sbase + toff + (uint32_t)(row * PITCH_B + kc * 16), src);
    }
    cp_commit();
}

__global__ void __launch_bounds__(512, 1)
sru_gemm_mma(const __half* __restrict__ Ah,
             const __half* __restrict__ Wh,
             const float* __restrict__ bias,
             __half* __restrict__ U)
{
    extern __shared__ char smem[];
    const uint32_t sb = smem_to_u32(smem);

    const int tid    = threadIdx.x;
    const int bid    = blockIdx.x;
    const int wid    = tid >> 5;
    const int lane   = tid & 31;
    const int group  = lane >> 2;
    const int tid4   = lane & 3;
    const int m_off  = (wid & 3) * 32;
    const int n_off  = (wid >> 2) * 64;

    const int a_row = (lane & 7) + ((lane >> 3) & 1) * 8;
    const int a_kb  = ((lane >> 4) & 1) * 8;
    const int b_row = (lane & 7) + ((lane >> 4) & 1) * 8;
    const int b_kb  = ((lane >> 3) & 1) * 8;

    const int nt = (bid < NTILE) ? ((NTILE - 1 - bid) / GPERS + 1) : 0;
    const int T  = nt * KST;
    if (T == 0) return;

    float acc[2][8][4];
#pragma unroll
    for (int mi = 0; mi < 2; mi++)
#pragma unroll
        for (int ni = 0; ni < 8; ni++)
#pragma unroll
            for (int q = 0; q < 4; q++) acc[mi][ni][q] = 0.f;

    issue_stage_g(sb, Ah, Wh, bid, 0, tid);
    if (T > 1) issue_stage_g(sb, Ah, Wh, bid, 1, tid);

#pragma unroll 1
    for (int g = 0; g < T; g++) {
        if (g == T - 1) cp_wait<0>(); else cp_wait<1>();
        __syncthreads();                       // one sync per stage
        if (g + 2 < T) issue_stage_g(sb, Ah, Wh, bid, g + 2, tid);

        const uint32_t st = sb + (uint32_t)(g % NSTAGE) * STAGE_B;
        const uint32_t sA = st;
        const uint32_t sB = st + A_TILE_B;

#pragma unroll
        for (int kk = 0; kk < BK / 16; kk++) {
            const int kbase = kk * 16;
            uint32_t a_f[2][4];
#pragma unroll
            for (int mi = 0; mi < 2; mi++) {
                uint32_t ao = (uint32_t)((m_off + mi * 16 + a_row) * PITCH_B
                                         + (kbase + a_kb) * 2);
                ldsm_x4(a_f[mi], sA + ao);
            }
            uint32_t b_f[4][4];
#pragma unroll
            for (int nj = 0; nj < 4; nj++) {
                uint32_t bo = (uint32_t)((n_off + nj * 16 + b_row) * PITCH_B
                                         + (kbase + b_kb) * 2);
                ldsm_x4(b_f[nj], sB + bo);
            }
#pragma unroll
            for (int mi = 0; mi < 2; mi++)
#pragma unroll
                for (int ni = 0; ni < 8; ni++) {
                    const int nj = ni >> 1, q = (ni & 1) * 2;
                    mma_fp16(acc[mi][ni], a_f[mi], b_f[nj][q], b_f[nj][q + 1]);
                }
        }

        if ((g & 7) == 7) {
            // ---- epilogue for tile g/8 (overlaps next tile's loads) ----
            const int tile = bid + (g >> 3) * GPERS;
            const int bn   = (tile % NTILE_N) * 256;
            const int bm   = (tile / NTILE_N) * 128;
            const bool gate = (bn >= HID);
#pragma unroll
            for (int mi = 0; mi < 2; mi++) {
                const int row0 = bm + m_off + mi * 16 + group;
#pragma unroll
                for (int ni = 0; ni < 8; ni++) {
                    const int col = bn + n_off + ni * 8 + tid4 * 2;
                    float u0 = acc[mi][ni][0], u1 = acc[mi][ni][1];
                    float u2 = acc[mi][ni][2], u3 = acc[mi][ni][3];
                    if (gate) {
                        const float bz0 = __ldg(&bias[col - HID]);
                        const float bz1 = __ldg(&bias[col + 1 - HID]);
                        u0 = __fdividef(1.0f, 1.0f + __expf(-(u0 + bz0)));
                        u1 = __fdividef(1.0f, 1.0f + __expf(-(u1 + bz1)));
                        u2 = __fdividef(1.0f, 1.0f + __expf(-(u2 + bz0)));
                        u3 = __fdividef(1.0f, 1.0f + __expf(-(u3 + bz1)));
                    }
                    *reinterpret_cast<__half2*>(&U[(size_t)row0 * NCOLS + col]) =
                        __floats2half2_rn(u0, u1);
                    *reinterpret_cast<__half2*>(&U[(size_t)(row0 + 8) * NCOLS + col]) =
                        __floats2half2_rn(u2, u3);
                    acc[mi][ni][0] = 0.f; acc[mi][ni][1] = 0.f;
                    acc[mi][ni][2] = 0.f; acc[mi][ni][3] = 0.f;
                }
            }
        }
    }
}

// ============================================================
// Chunked parallel scan, half2 lanes, 64 chunks.
// pass1: per-chunk (P = prod f, S = local end state).
// pass3: computes its own Cin prologue from P/S (pass2 eliminated;
//        identical fma chain order -> bit-identical results).
// ============================================================
__global__ void __launch_bounds__(256)
scan_pass1(const __half* __restrict__ U, float* __restrict__ P, float* __restrict__ S) {
    int gid   = blockIdx.x * blockDim.x + threadIdx.x;   // 0 .. NCH*BH2-1
    int lane2 = gid & (BH2 - 1);
    int kc    = gid >> 12;                               // BH2 = 4096
    int b  = lane2 >> 8;                                 // HID/2 = 256
    int h2 = lane2 & 255;
    int l0 = kc * CHL;
    const __half2* U2 = reinterpret_cast<const __half2*>(U);

    float c0 = 0.f, c1 = 0.f, p0 = 1.f, p1 = 1.f;
    for (int l = l0; l < l0 + CHL; l += SUNROLL) {
        float2 f[SUNROLL], xt[SUNROLL];
#pragma unroll
        for (int u = 0; u < SUNROLL; u++) {
            size_t base = ((size_t)(l + u) * BATCH + b) * (NCOLS / 2) + h2;
            xt[u] = __half22float2(U2[base]);
            f [u] = __half22float2(U2[base + HID / 2]);
        }
#pragma unroll
        for (int u = 0; u < SUNROLL; u++) {
            c0 = fmaf(f[u].x, c0 - xt[u].x, xt[u].x);
            c1 = fmaf(f[u].y, c1 - xt[u].y, xt[u].y);
            p0 *= f[u].x;
            p1 *= f[u].y;
        }
    }
    size_t o2 = (size_t)kc * BH2 + lane2;
    reinterpret_cast<float2*>(P)[o2] = make_float2(p0, p1);
    reinterpret_cast<float2*>(S)[o2] = make_float2(c0, c1);
}

__global__ void __launch_bounds__(256)
scan_pass3(const __half* __restrict__ U, const __half* __restrict__ xin,
           const float* __restrict__ P, const float* __restrict__ S,
           __half* __restrict__ hout) {
    int gid   = blockIdx.x * blockDim.x + threadIdx.x;
    int lane2 = gid & (BH2 - 1);
    int kc    = gid >> 12;
    int b  = lane2 >> 8;
    int h2 = lane2 & 255;
    int l0 = kc * CHL;
    const __half2* U2 = reinterpret_cast<const __half2*>(U);
    const __half2* X2 = reinterpret_cast<const __half2*>(xin);
    __half2* H2 = reinterpret_cast<__half2*>(hout);
    const float2* P2 = reinterpret_cast<const float2*>(P);
    const float2* S2 = reinterpret_cast<const float2*>(S);

    // ---- Cin prologue: serial combine over chunks 0..kc-1 (L2-resident,
    //      unroll-4 batched loads; same fma order as the old pass2) ----
    float c0 = 0.f, c1 = 0.f;
#pragma unroll 4
    for (int k = 0; k < kc; k++) {
        float2 pv = P2[(size_t)k * BH2 + lane2];
        float2 sv = S2[(size_t)k * BH2 + lane2];
        c0 = fmaf(pv.x, c0, sv.x);
        c1 = fmaf(pv.y, c1, sv.y);
    }

    for (int l = l0; l < l0 + CHL; l += SUNROLL) {
        float2 f[SUNROLL], xt[SUNROLL], r[SUNROLL], xv[SUNROLL];
#pragma unroll
        for (int u = 0; u < SUNROLL; u++) {
            size_t row  = (size_t)(l + u) * BATCH + b;
            size_t base = row * (NCOLS / 2) + h2;
            xt[u] = __half22float2(U2[base]);
            f [u] = __half22float2(U2[base + HID / 2]);
            r [u] = __half22float2(U2[base + HID]);
            xv[u] = __half22float2(X2[row * (HID / 2) + h2]);
        }
#pragma unroll
        for (int u = 0; u < SUNROLL; u++) {
            c0 = fmaf(f[u].x, c0 - xt[u].x, xt[u].x);
            c1 = fmaf(f[u].y, c1 - xt[u].y, xt[u].y);
            float h0 = fmaf(r[u].x, c0 - xv[u].x, xv[u].x);
            float h1 = fmaf(r[u].y, c1 - xv[u].y, xv[u].y);
            size_t row = (size_t)(l + u) * BATCH + b;
            H2[row * (HID / 2) + h2] = __floats2half2_rn(h0, h1);
        }
    }
}

// ============================================================
// Final FC (half2 activation reads, fp32 weights/accum)
// ============================================================
__global__ void __launch_bounds__(256)
fc_kernel(const __half* __restrict__ Hf, const float* __restrict__ fcW,
          const float* __restrict__ fcb, float* __restrict__ out) {
    __shared__ float Wsm[OUT_F * HID];
    int tid = threadIdx.x;
    for (int i = tid; i < OUT_F * HID; i += 256) Wsm[i] = fcW[i];
    __syncthreads();

    int warp = tid >> 5, lane = tid & 31;
    int row = blockIdx.x * 8 + warp;
    const __half2* hp = reinterpret_cast<const __half2*>(Hf + (size_t)row * HID);

    float acc[OUT_F];
#pragma unroll
    for (int n = 0; n < OUT_F; n++) acc[n] = 0.f;

    for (int k2 = lane; k2 < HID / 2; k2 += 32) {
        float2 xv = __half22float2(hp[k2]);
#pragma unroll
        for (int n = 0; n < OUT_F; n++) {
            acc[n] = fmaf(xv.x, Wsm[n * HID + 2 * k2],     acc[n]);
            acc[n] = fmaf(xv.y, Wsm[n * HID + 2 * k2 + 1], acc[n]);
        }
    }
#pragma unroll
    for (int n = 0; n < OUT_F; n++) {
        float v = acc[n];
        v += __shfl_xor_sync(0xFFFFFFFFu, v, 16);
        v += __shfl_xor_sync(0xFFFFFFFFu, v, 8);
        v += __shfl_xor_sync(0xFFFFFFFFu, v, 4);
        v += __shfl_xor_sync(0xFFFFFFFFu, v, 2);
        v += __shfl_xor_sync(0xFFFFFFFFu, v, 1);
        if (lane == 0) out[(size_t)row * OUT_F + n] = v + fcb[n];
    }
}

// ============================================================
// Host launcher (graph-capturable: kernel launches only)
// ============================================================
extern "C" void kernel_launch(void* const* d_in, const int* in_sizes, int n_in,
                              void* d_out, int out_size) {
    const float* x    = (const float*)d_in[0];
    const float* Ws   = (const float*)d_in[1];
    const float* bs   = (const float*)d_in[2];
    const float* fcW  = (const float*)d_in[3];
    const float* fcb  = (const float*)d_in[4];
    float* out        = (float*)d_out;

    float *P, *S;
    __half *U, *A0, *A1, *Wh;
    cudaGetSymbolAddress((void**)&U,   g_U);
    cudaGetSymbolAddress((void**)&A0,  g_A0);
    cudaGetSymbolAddress((void**)&A1,  g_A1);
    cudaGetSymbolAddress((void**)&Wh,  g_Wh);
    cudaGetSymbolAddress((void**)&P,   g_P);
    cudaGetSymbolAddress((void**)&S,   g_S);

    cudaFuncSetAttribute(sru_gemm_mma,
                         cudaFuncAttributeMaxDynamicSharedMemorySize, SMEM_GEMM);

    const int nA4   = MROWS * HID / 4;
    const int nWall = NLAY * NCOLS * HID / 4;
    const int scan_grid = NCH * BH2 / 256;    // 1024

    // One-time: convert all weights and layer-0 activations to fp16.
    convert_fp16<<<(nWall + 255) / 256, 256>>>(Ws, Wh, nWall);
    convert_fp16<<<(nA4 + 255) / 256, 256>>>(x, A0, nA4);

    __half* cur = A0;
    __half* nxt = A1;
    for (int l = 0; l < NLAY; l++) {
        const size_t woff = (size_t)l * NCOLS * HID;
        sru_gemm_mma<<<GPERS, 512, SMEM_GEMM>>>(cur, Wh + woff,
                                                bs + (size_t)l * (2 * HID), U);
        scan_pass1<<<scan_grid, 256>>>(U, P, S);
        scan_pass3<<<scan_grid, 256>>>(U, cur, P, S, nxt);
        __half* t = cur; cur = nxt; nxt = t;
    }
    fc_kernel<<<MROWS / 8, 256>>>(cur, fcW, fcb, out);
}

// round 15
// speedup vs baseline: 1.0361x; 1.0361x over previous
#include <cuda_runtime.h>
#include <cuda_fp16.h>
#include <cstdint>
#include <cstddef>

// Problem constants
#define SEQ   2048
#define BATCH 16
#define HID   512
#define OUT_F 10
#define NLAY  5
#define MROWS (SEQ * BATCH)      // 32768
#define NCOLS (3 * HID)          // 1536
#define BH    (BATCH * HID)      // 8192
#define BH2   (BH / 2)           // 4096

// Scan chunking (64 chunks x 32 steps: single-wave wide grid)
#define NCH   64
#define CHL   (SEQ / NCH)        // 32 timesteps per chunk
#define SUNROLL 8

// ---------------- device scratch (no allocations allowed) ----------------
__device__ __half g_U [(size_t)MROWS * NCOLS];         // 96 MB: [xt | f | r] fp16
__device__ __half g_A0[(size_t)MROWS * HID];           // 32 MB activations ping
__device__ __half g_A1[(size_t)MROWS * HID];           // 32 MB activations pong
__device__ __half g_Wh[(size_t)NLAY * NCOLS * HID];    // 7.5 MB weights fp16
__device__ float g_P  [(size_t)NCH * BH];              // 2 MB chunk f-products
__device__ float g_S  [(size_t)NCH * BH];              // 2 MB chunk end-states
__device__ float g_Cin[(size_t)NCH * BH];              // 2 MB chunk initial c

// ================= arch-neutral PTX helpers (sm_80+ features only) =======
__device__ __forceinline__ uint32_t smem_to_u32(const void* p) {
    uint32_t a;
    asm("{ .reg .u64 t; cvta.to.shared.u64 t, %1; cvt.u32.u64 %0, t; }"
        : "=r"(a) : "l"(p));
    return a;
}
__device__ __forceinline__ void cp16(uint32_t saddr, const void* g) {
    asm volatile("cp.async.cg.shared.global [%0], [%1], 16;"
                 :: "r"(saddr), "l"(g) : "memory");
}
__device__ __forceinline__ void cp_commit() {
    asm volatile("cp.async.commit_group;" ::: "memory");
}
template <int N>
__device__ __forceinline__ void cp_wait() {
    asm volatile("cp.async.wait_group %0;" :: "n"(N) : "memory");
}
__device__ __forceinline__ void ldsm_x4(uint32_t (&r)[4], uint32_t addr) {
    asm volatile("ldmatrix.sync.aligned.m8n8.x4.shared.b16 {%0,%1,%2,%3}, [%4];"
                 : "=r"(r[0]), "=r"(r[1]), "=r"(r[2]), "=r"(r[3])
                 : "r"(addr));
}
__device__ __forceinline__ void mma_fp16(float (&d)[4], const uint32_t (&a)[4],
                                         uint32_t b0, uint32_t b1) {
    asm volatile(
        "mma.sync.aligned.m16n8k16.row.col.f32.f16.f16.f32 "
        "{%0,%1,%2,%3}, {%4,%5,%6,%7}, {%8,%9}, {%0,%1,%2,%3};"
        : "+f"(d[0]), "+f"(d[1]), "+f"(d[2]), "+f"(d[3])
        : "r"(a[0]), "r"(a[1]), "r"(a[2]), "r"(a[3]), "r"(b0), "r"(b1));
}

// ============================================================
// fp32 -> fp16 convert.  n4 = element_count / 4.
// ============================================================
__global__ void convert_fp16(const float* __restrict__ in,
                             __half* __restrict__ out, int n4) {
    int i = blockIdx.x * blockDim.x + threadIdx.x;
    if (i >= n4) return;
    float4 v = reinterpret_cast<const float4*>(in)[i];
    __half h[4];
    h[0] = __float2half_rn(v.x);  h[1] = __float2half_rn(v.y);
    h[2] = __float2half_rn(v.z);  h[3] = __float2half_rn(v.w);
    reinterpret_cast<uint2*>(out)[i] = *reinterpret_cast<uint2*>(h);
}

// ============================================================
// Persistent tensor-core GEMM via mma.sync (fp16, fp32 accum):
//   U[M=32768, N=1536] = A[M,512] * W[N,512]^T   (U stored fp16)
// Grid = GPERS persistent CTAs; cross-tile cp.async ring, one sync/stage.
// CTA tile 128(M) x 256(N), BK=64, 16 warps (4x4), warp tile 32x64.
// Epilogue: cols >= 512 -> sigmoid(u + bias[n-512]); half2 stores.
// (At ~92% of the sm_100 legacy HMMA ceiling — unchanged, protected.)
// ============================================================
#define BK 64
#define PITCH_B 144
#define A_TILE_B (128 * PITCH_B)          // 18432 B
#define B_TILE_B (256 * PITCH_B)          // 36864 B
#define STAGE_B (A_TILE_B + B_TILE_B)     // 55296 B
#define NSTAGE 3
#define SMEM_GEMM (NSTAGE * STAGE_B)      // 165888 B
#define NTILE_N 6                         // 1536 / 256
#define NTILE   (NTILE_N * (MROWS / 128)) // 1536 tiles
#define KST     8                         // K-stages per tile (512/64)
#define GPERS   148                       // persistent CTAs

__device__ __forceinline__ void issue_stage_g(
    uint32_t sb, const __half* __restrict__ Ah,
    const __half* __restrict__ Wh,
    int bid, int g, int tid)
{
    const int i    = g >> 3;
    const int s    = g & 7;
    const int tile = bid + i * GPERS;
    const int bn   = (tile % NTILE_N) * 256;
    const int bm   = (tile / NTILE_N) * 128;
    const int k0   = s * BK;
    const uint32_t sbase = sb + (uint32_t)(g % NSTAGE) * STAGE_B;
#pragma unroll
    for (int q = 0; q < 6; q++) {
        int c = tid + q * 512;
        const __half* src;
        uint32_t toff;
        int row, kc;
        if (q < 2) {                       // A: 128 rows
            row = c >> 3;  kc = c & 7;
            src  = Ah + (size_t)(bm + row) * HID + k0 + kc * 8;
            toff = 0u;
        } else {                           // W: 256 rows
            int idx = c - 1024;
            row = idx >> 3;  kc = idx & 7;
            src  = Wh + (size_t)(bn + row) * HID + k0 + kc * 8;
            toff = (uint32_t)A_TILE_B;
        }
        cp16(sbase + toff + (uint32_t)(row * PITCH_B + kc * 16), src);
    }
    cp_commit();
}

__global__ void __launch_bounds__(512, 1)
sru_gemm_mma(const __half* __restrict__ Ah,
             const __half* __restrict__ Wh,
             const float* __restrict__ bias,
             __half* __restrict__ U)
{
    extern __shared__ char smem[];
    const uint32_t sb = smem_to_u32(smem);

    const int tid    = threadIdx.x;
    const int bid    = blockIdx.x;
    const int wid    = tid >> 5;
    const int lane   = tid & 31;
    const int group  = lane >> 2;
    const int tid4   = lane & 3;
    const int m_off  = (wid & 3) * 32;
    const int n_off  = (wid >> 2) * 64;

    const int a_row = (lane & 7) + ((lane >> 3) & 1) * 8;
    const int a_kb  = ((lane >> 4) & 1) * 8;
    const int b_row = (lane & 7) + ((lane >> 4) & 1) * 8;
    const int b_kb  = ((lane >> 3) & 1) * 8;

    const int nt = (bid < NTILE) ? ((NTILE - 1 - bid) / GPERS + 1) : 0;
    const int T  = nt * KST;
    if (T == 0) return;

    float acc[2][8][4];
#pragma unroll
    for (int mi = 0; mi < 2; mi++)
#pragma unroll
        for (int ni = 0; ni < 8; ni++)
#pragma unroll
            for (int q = 0; q < 4; q++) acc[mi][ni][q] = 0.f;

    issue_stage_g(sb, Ah, Wh, bid, 0, tid);
    if (T > 1) issue_stage_g(sb, Ah, Wh, bid, 1, tid);

#pragma unroll 1
    for (int g = 0; g < T; g++) {
        if (g == T - 1) cp_wait<0>(); else cp_wait<1>();
        __syncthreads();                       // one sync per stage
        if (g + 2 < T) issue_stage_g(sb, Ah, Wh, bid, g + 2, tid);

        const uint32_t st = sb + (uint32_t)(g % NSTAGE) * STAGE_B;
        const uint32_t sA = st;
        const uint32_t sB = st + A_TILE_B;

#pragma unroll
        for (int kk = 0; kk < BK / 16; kk++) {
            const int kbase = kk * 16;
            uint32_t a_f[2][4];
#pragma unroll
            for (int mi = 0; mi < 2; mi++) {
                uint32_t ao = (uint32_t)((m_off + mi * 16 + a_row) * PITCH_B
                                         + (kbase + a_kb) * 2);
                ldsm_x4(a_f[mi], sA + ao);
            }
            uint32_t b_f[4][4];
#pragma unroll
            for (int nj = 0; nj < 4; nj++) {
                uint32_t bo = (uint32_t)((n_off + nj * 16 + b_row) * PITCH_B
                                         + (kbase + b_kb) * 2);
                ldsm_x4(b_f[nj], sB + bo);
            }
#pragma unroll
            for (int mi = 0; mi < 2; mi++)
#pragma unroll
                for (int ni = 0; ni < 8; ni++) {
                    const int nj = ni >> 1, q = (ni & 1) * 2;
                    mma_fp16(acc[mi][ni], a_f[mi], b_f[nj][q], b_f[nj][q + 1]);
                }
        }

        if ((g & 7) == 7) {
            // ---- epilogue for tile g/8 (overlaps next tile's loads) ----
            const int tile = bid + (g >> 3) * GPERS;
            const int bn   = (tile % NTILE_N) * 256;
            const int bm   = (tile / NTILE_N) * 128;
            const bool gate = (bn >= HID);
#pragma unroll
            for (int mi = 0; mi < 2; mi++) {
                const int row0 = bm + m_off + mi * 16 + group;
#pragma unroll
                for (int ni = 0; ni < 8; ni++) {
                    const int col = bn + n_off + ni * 8 + tid4 * 2;
                    float u0 = acc[mi][ni][0], u1 = acc[mi][ni][1];
                    float u2 = acc[mi][ni][2], u3 = acc[mi][ni][3];
                    if (gate) {
                        const float bz0 = __ldg(&bias[col - HID]);
                        const float bz1 = __ldg(&bias[col + 1 - HID]);
                        u0 = __fdividef(1.0f, 1.0f + __expf(-(u0 + bz0)));
                        u1 = __fdividef(1.0f, 1.0f + __expf(-(u1 + bz1)));
                        u2 = __fdividef(1.0f, 1.0f + __expf(-(u2 + bz0)));
                        u3 = __fdividef(1.0f, 1.0f + __expf(-(u3 + bz1)));
                    }
                    *reinterpret_cast<__half2*>(&U[(size_t)row0 * NCOLS + col]) =
                        __floats2half2_rn(u0, u1);
                    *reinterpret_cast<__half2*>(&U[(size_t)(row0 + 8) * NCOLS + col]) =
                        __floats2half2_rn(u2, u3);
                    acc[mi][ni][0] = 0.f; acc[mi][ni][1] = 0.f;
                    acc[mi][ni][2] = 0.f; acc[mi][ni][3] = 0.f;
                }
            }
        }
    }
}

// ============================================================
// Chunked parallel scan, half2 lanes, 64 chunks (R13 structure:
// separate pass2 — the fused prologue variant regressed in R14).
// ============================================================
__global__ void __launch_bounds__(256)
scan_pass1(const __half* __restrict__ U, float* __restrict__ P, float* __restrict__ S) {
    int gid   = blockIdx.x * blockDim.x + threadIdx.x;   // 0 .. NCH*BH2-1
    int lane2 = gid & (BH2 - 1);
    int kc    = gid >> 12;                               // BH2 = 4096
    int b  = lane2 >> 8;                                 // HID/2 = 256
    int h2 = lane2 & 255;
    int l0 = kc * CHL;
    const __half2* U2 = reinterpret_cast<const __half2*>(U);

    float c0 = 0.f, c1 = 0.f, p0 = 1.f, p1 = 1.f;
    for (int l = l0; l < l0 + CHL; l += SUNROLL) {
        float2 f[SUNROLL], xt[SUNROLL];
#pragma unroll
        for (int u = 0; u < SUNROLL; u++) {
            size_t base = ((size_t)(l + u) * BATCH + b) * (NCOLS / 2) + h2;
            xt[u] = __half22float2(U2[base]);
            f [u] = __half22float2(U2[base + HID / 2]);
        }
#pragma unroll
        for (int u = 0; u < SUNROLL; u++) {
            c0 = fmaf(f[u].x, c0 - xt[u].x, xt[u].x);
            c1 = fmaf(f[u].y, c1 - xt[u].y, xt[u].y);
            p0 *= f[u].x;
            p1 *= f[u].y;
        }
    }
    size_t o2 = (size_t)kc * BH2 + lane2;
    reinterpret_cast<float2*>(P)[o2] = make_float2(p0, p1);
    reinterpret_cast<float2*>(S)[o2] = make_float2(c0, c1);
}

__global__ void __launch_bounds__(256)
scan_pass2(const float* __restrict__ P, const float* __restrict__ S,
           float* __restrict__ Cin) {
    int lane = blockIdx.x * blockDim.x + threadIdx.x;   // 0..BH-1
    float c = 0.f;
#pragma unroll
    for (int k = 0; k < NCH; k++) {
        Cin[(size_t)k * BH + lane] = c;
        c = fmaf(P[(size_t)k * BH + lane], c, S[(size_t)k * BH + lane]);
    }
}

__global__ void __launch_bounds__(256)
scan_pass3(const __half* __restrict__ U, const __half* __restrict__ xin,
           const float* __restrict__ Cin, __half* __restrict__ hout) {
    int gid   = blockIdx.x * blockDim.x + threadIdx.x;
    int lane2 = gid & (BH2 - 1);
    int kc    = gid >> 12;
    int b  = lane2 >> 8;
    int h2 = lane2 & 255;
    int l0 = kc * CHL;
    const __half2* U2 = reinterpret_cast<const __half2*>(U);
    const __half2* X2 = reinterpret_cast<const __half2*>(xin);
    __half2* H2 = reinterpret_cast<__half2*>(hout);

    float2 cin = reinterpret_cast<const float2*>(Cin)[(size_t)kc * BH2 + lane2];
    float c0 = cin.x, c1 = cin.y;
    for (int l = l0; l < l0 + CHL; l += SUNROLL) {
        float2 f[SUNROLL], xt[SUNROLL], r[SUNROLL], xv[SUNROLL];
#pragma unroll
        for (int u = 0; u < SUNROLL; u++) {
            size_t row  = (size_t)(l + u) * BATCH + b;
            size_t base = row * (NCOLS / 2) + h2;
            xt[u] = __half22float2(U2[base]);
            f [u] = __half22float2(U2[base + HID / 2]);
            r [u] = __half22float2(U2[base + HID]);
            xv[u] = __half22float2(X2[row * (HID / 2) + h2]);
        }
#pragma unroll
        for (int u = 0; u < SUNROLL; u++) {
            c0 = fmaf(f[u].x, c0 - xt[u].x, xt[u].x);
            c1 = fmaf(f[u].y, c1 - xt[u].y, xt[u].y);
            float h0 = fmaf(r[u].x, c0 - xv[u].x, xv[u].x);
            float h1 = fmaf(r[u].y, c1 - xv[u].y, xv[u].y);
            size_t row = (size_t)(l + u) * BATCH + b;
            H2[row * (HID / 2) + h2] = __floats2half2_rn(h0, h1);
        }
    }
}

// ============================================================
// Final FC: 4 rows per warp (grid 4096 -> 1024 blocks, cutting
// fc_W smem-staging L2 traffic 80 MB -> 20 MB).
// ============================================================
#define FC_RPW 4
__global__ void __launch_bounds__(256)
fc_kernel(const __half* __restrict__ Hf, const float* __restrict__ fcW,
          const float* __restrict__ fcb, float* __restrict__ out) {
    __shared__ float Wsm[OUT_F * HID];
    int tid = threadIdx.x;
    for (int i = tid; i < OUT_F * HID; i += 256) Wsm[i] = fcW[i];
    __syncthreads();

    int warp = tid >> 5, lane = tid & 31;
    int row0 = (blockIdx.x * 8 + warp) * FC_RPW;

#pragma unroll
    for (int rr = 0; rr < FC_RPW; rr++) {
        int row = row0 + rr;
        const __half2* hp = reinterpret_cast<const __half2*>(Hf + (size_t)row * HID);

        float acc[OUT_F];
#pragma unroll
        for (int n = 0; n < OUT_F; n++) acc[n] = 0.f;

        for (int k2 = lane; k2 < HID / 2; k2 += 32) {
            float2 xv = __half22float2(hp[k2]);
#pragma unroll
            for (int n = 0; n < OUT_F; n++) {
                acc[n] = fmaf(xv.x, Wsm[n * HID + 2 * k2],     acc[n]);
                acc[n] = fmaf(xv.y, Wsm[n * HID + 2 * k2 + 1], acc[n]);
            }
        }
#pragma unroll
        for (int n = 0; n < OUT_F; n++) {
            float v = acc[n];
            v += __shfl_xor_sync(0xFFFFFFFFu, v, 16);
            v += __shfl_xor_sync(0xFFFFFFFFu, v, 8);
            v += __shfl_xor_sync(0xFFFFFFFFu, v, 4);
            v += __shfl_xor_sync(0xFFFFFFFFu, v, 2);
            v += __shfl_xor_sync(0xFFFFFFFFu, v, 1);
            if (lane == 0) out[(size_t)row * OUT_F + n] = v + fcb[n];
        }
    }
}

// ============================================================
// Host launcher (graph-capturable: kernel launches only)
// ============================================================
extern "C" void kernel_launch(void* const* d_in, const int* in_sizes, int n_in,
                              void* d_out, int out_size) {
    const float* x    = (const float*)d_in[0];
    const float* Ws   = (const float*)d_in[1];
    const float* bs   = (const float*)d_in[2];
    const float* fcW  = (const float*)d_in[3];
    const float* fcb  = (const float*)d_in[4];
    float* out        = (float*)d_out;

    float *P, *S, *Cin;
    __half *U, *A0, *A1, *Wh;
    cudaGetSymbolAddress((void**)&U,   g_U);
    cudaGetSymbolAddress((void**)&A0,  g_A0);
    cudaGetSymbolAddress((void**)&A1,  g_A1);
    cudaGetSymbolAddress((void**)&Wh,  g_Wh);
    cudaGetSymbolAddress((void**)&P,   g_P);
    cudaGetSymbolAddress((void**)&S,   g_S);
    cudaGetSymbolAddress((void**)&Cin, g_Cin);

    cudaFuncSetAttribute(sru_gemm_mma,
                         cudaFuncAttributeMaxDynamicSharedMemorySize, SMEM_GEMM);

    const int nA4   = MROWS * HID / 4;
    const int nWall = NLAY * NCOLS * HID / 4;
    const int scan_grid = NCH * BH2 / 256;    // 1024

    // One-time: convert all weights and layer-0 activations to fp16.
    convert_fp16<<<(nWall + 255) / 256, 256>>>(Ws, Wh, nWall);
    convert_fp16<<<(nA4 + 255) / 256, 256>>>(x, A0, nA4);

    __half* cur = A0;
    __half* nxt = A1;
    for (int l = 0; l < NLAY; l++) {
        const size_t woff = (size_t)l * NCOLS * HID;
        sru_gemm_mma<<<GPERS, 512, SMEM_GEMM>>>(cur, Wh + woff,
                                                bs + (size_t)l * (2 * HID), U);
        scan_pass1<<<scan_grid, 256>>>(U, P, S);
        scan_pass2<<<BH / 256, 256>>>(P, S, Cin);
        scan_pass3<<<scan_grid, 256>>>(U, cur, Cin, nxt);
        __half* t = cur; cur = nxt; nxt = t;
    }
    fc_kernel<<<MROWS / (8 * FC_RPW), 256>>>(cur, fcW, fcb, out);
}

// round 17
// speedup vs baseline: 1.0467x; 1.0102x over previous
#include <cuda_runtime.h>
#include <cuda_fp16.h>
#include <cstdint>
#include <cstddef>

// Problem constants
#define SEQ   2048
#define BATCH 16
#define HID   512
#define OUT_F 10
#define NLAY  5
#define MROWS (SEQ * BATCH)      // 32768
#define NCOLS (3 * HID)          // 1536
#define BH    (BATCH * HID)      // 8192
#define BH2   (BH / 2)           // 4096

// Scan chunking (64 chunks x 32 steps: single-wave wide grid)
#define NCH   64
#define CHL   (SEQ / NCH)        // 32 timesteps per chunk
#define SUNROLL 8

// ---------------- device scratch (no allocations allowed) ----------------
__device__ __half g_U [(size_t)MROWS * NCOLS];         // 96 MB: [xt | f | r] fp16
__device__ __half g_A0[(size_t)MROWS * HID];           // 32 MB activations ping
__device__ __half g_A1[(size_t)MROWS * HID];           // 32 MB activations pong
__device__ __half g_Wh[(size_t)NLAY * NCOLS * HID];    // 7.5 MB weights fp16
__device__ float g_P  [(size_t)NCH * BH];              // 2 MB chunk f-products
__device__ float g_S  [(size_t)NCH * BH];              // 2 MB chunk end-states
__device__ float g_Cin[(size_t)NCH * BH];              // 2 MB chunk initial c

// ================= arch-neutral PTX helpers (sm_80+ features only) =======
__device__ __forceinline__ uint32_t smem_to_u32(const void* p) {
    uint32_t a;
    asm("{ .reg .u64 t; cvta.to.shared.u64 t, %1; cvt.u32.u64 %0, t; }"
        : "=r"(a) : "l"(p));
    return a;
}
__device__ __forceinline__ void cp16(uint32_t saddr, const void* g) {
    asm volatile("cp.async.cg.shared.global [%0], [%1], 16;"
                 :: "r"(saddr), "l"(g) : "memory");
}
__device__ __forceinline__ void cp_commit() {
    asm volatile("cp.async.commit_group;" ::: "memory");
}
template <int N>
__device__ __forceinline__ void cp_wait() {
    asm volatile("cp.async.wait_group %0;" :: "n"(N) : "memory");
}
__device__ __forceinline__ void ldsm_x4(uint32_t (&r)[4], uint32_t addr) {
    asm volatile("ldmatrix.sync.aligned.m8n8.x4.shared.b16 {%0,%1,%2,%3}, [%4];"
                 : "=r"(r[0]), "=r"(r[1]), "=r"(r[2]), "=r"(r[3])
                 : "r"(addr));
}
__device__ __forceinline__ void mma_fp16(float (&d)[4], const uint32_t (&a)[4],
                                         uint32_t b0, uint32_t b1) {
    asm volatile(
        "mma.sync.aligned.m16n8k16.row.col.f32.f16.f16.f32 "
        "{%0,%1,%2,%3}, {%4,%5,%6,%7}, {%8,%9}, {%0,%1,%2,%3};"
        : "+f"(d[0]), "+f"(d[1]), "+f"(d[2]), "+f"(d[3])
        : "r"(a[0]), "r"(a[1]), "r"(a[2]), "r"(a[3]), "r"(b0), "r"(b1));
}

// ============================================================
// fp32 -> fp16 convert.  n4 = element_count / 4.
// ============================================================
__global__ void convert_fp16(const float* __restrict__ in,
                             __half* __restrict__ out, int n4) {
    int i = blockIdx.x * blockDim.x + threadIdx.x;
    if (i >= n4) return;
    float4 v = reinterpret_cast<const float4*>(in)[i];
    __half h[4];
    h[0] = __float2half_rn(v.x);  h[1] = __float2half_rn(v.y);
    h[2] = __float2half_rn(v.z);  h[3] = __float2half_rn(v.w);
    reinterpret_cast<uint2*>(out)[i] = *reinterpret_cast<uint2*>(h);
}

// ============================================================
// Persistent tensor-core GEMM via mma.sync (fp16, fp32 accum):
//   U[M=32768, N=1536] = A[M,512] * W[N,512]^T   (U stored fp16)
// Grid = GPERS persistent CTAs; cross-tile 4-deep cp.async ring,
// one __syncthreads per stage.
// CTA tile 128(M) x 256(N), BK=64, 16 warps (4x4), warp tile 32x64.
// Epilogue: cols >= 512 -> sigmoid(u + bias[n-512]); half2 stores.
// (At ~94% of the sm_100 legacy HMMA issue floor.)
// ============================================================
#define BK 64
#define PITCH_B 144
#define A_TILE_B (128 * PITCH_B)          // 18432 B
#define B_TILE_B (256 * PITCH_B)          // 36864 B
#define STAGE_B (A_TILE_B + B_TILE_B)     // 55296 B
#define NSTAGE 4
#define SMEM_GEMM (NSTAGE * STAGE_B)      // 221184 B
#define NTILE_N 6                         // 1536 / 256
#define NTILE   (NTILE_N * (MROWS / 128)) // 1536 tiles
#define KST     8                         // K-stages per tile (512/64)
#define GPERS   148                       // persistent CTAs

__device__ __forceinline__ void issue_stage_g(
    uint32_t sb, const __half* __restrict__ Ah,
    const __half* __restrict__ Wh,
    int bid, int g, int tid)
{
    const int i    = g >> 3;
    const int s    = g & 7;
    const int tile = bid + i * GPERS;
    const int bn   = (tile % NTILE_N) * 256;
    const int bm   = (tile / NTILE_N) * 128;
    const int k0   = s * BK;
    const uint32_t sbase = sb + (uint32_t)(g % NSTAGE) * STAGE_B;
#pragma unroll
    for (int q = 0; q < 6; q++) {
        int c = tid + q * 512;
        const __half* src;
        uint32_t toff;
        int row, kc;
        if (q < 2) {                       // A: 128 rows
            row = c >> 3;  kc = c & 7;
            src  = Ah + (size_t)(bm + row) * HID + k0 + kc * 8;
            toff = 0u;
        } else {                           // W: 256 rows
            int idx = c - 1024;
            row = idx >> 3;  kc = idx & 7;
            src  = Wh + (size_t)(bn + row) * HID + k0 + kc * 8;
            toff = (uint32_t)A_TILE_B;
        }
        cp16(sbase + toff + (uint32_t)(row * PITCH_B + kc * 16), src);
    }
    cp_commit();
}

__global__ void __launch_bounds__(512, 1)
sru_gemm_mma(const __half* __restrict__ Ah,
             const __half* __restrict__ Wh,
             const float* __restrict__ bias,
             __half* __restrict__ U)
{
    extern __shared__ char smem[];
    const uint32_t sb = smem_to_u32(smem);

    const int tid    = threadIdx.x;
    const int bid    = blockIdx.x;
    const int wid    = tid >> 5;
    const int lane   = tid & 31;
    const int group  = lane >> 2;
    const int tid4   = lane & 3;
    const int m_off  = (wid & 3) * 32;
    const int n_off  = (wid >> 2) * 64;

    const int a_row = (lane & 7) + ((lane >> 3) & 1) * 8;
    const int a_kb  = ((lane >> 4) & 1) * 8;
    const int b_row = (lane & 7) + ((lane >> 4) & 1) * 8;
    const int b_kb  = ((lane >> 3) & 1) * 8;

    const int nt = (bid < NTILE) ? ((NTILE - 1 - bid) / GPERS + 1) : 0;
    const int T  = nt * KST;
    if (T == 0) return;

    float acc[2][8][4];
#pragma unroll
    for (int mi = 0; mi < 2; mi++)
#pragma unroll
        for (int ni = 0; ni < 8; ni++)
#pragma unroll
            for (int q = 0; q < 4; q++) acc[mi][ni][q] = 0.f;

    issue_stage_g(sb, Ah, Wh, bid, 0, tid);
    if (T > 1) issue_stage_g(sb, Ah, Wh, bid, 1, tid);
    if (T > 2) issue_stage_g(sb, Ah, Wh, bid, 2, tid);

#pragma unroll 1
    for (int g = 0; g < T; g++) {
        // wait until stage g is complete (keep up to 2 newer groups in flight)
        const int rem = T - 1 - g;
        if (rem >= 2)      cp_wait<2>();
        else if (rem == 1) cp_wait<1>();
        else               cp_wait<0>();
        __syncthreads();                       // one sync per stage
        if (g + 3 < T) issue_stage_g(sb, Ah, Wh, bid, g + 3, tid);

        const uint32_t st = sb + (uint32_t)(g % NSTAGE) * STAGE_B;
        const uint32_t sA = st;
        const uint32_t sB = st + A_TILE_B;

#pragma unroll
        for (int kk = 0; kk < BK / 16; kk++) {
            const int kbase = kk * 16;
            uint32_t a_f[2][4];
#pragma unroll
            for (int mi = 0; mi < 2; mi++) {
                uint32_t ao = (uint32_t)((m_off + mi * 16 + a_row) * PITCH_B
                                         + (kbase + a_kb) * 2);
                ldsm_x4(a_f[mi], sA + ao);
            }
            uint32_t b_f[4][4];
#pragma unroll
            for (int nj = 0; nj < 4; nj++) {
                uint32_t bo = (uint32_t)((n_off + nj * 16 + b_row) * PITCH_B
                                         + (kbase + b_kb) * 2);
                ldsm_x4(b_f[nj], sB + bo);
            }
#pragma unroll
            for (int mi = 0; mi < 2; mi++)
#pragma unroll
                for (int ni = 0; ni < 8; ni++) {
                    const int nj = ni >> 1, q = (ni & 1) * 2;
                    mma_fp16(acc[mi][ni], a_f[mi], b_f[nj][q], b_f[nj][q + 1]);
                }
        }

        if ((g & 7) == 7) {
            // ---- epilogue for tile g/8 (overlaps next tile's loads) ----
            const int tile = bid + (g >> 3) * GPERS;
            const int bn   = (tile % NTILE_N) * 256;
            const int bm   = (tile / NTILE_N) * 128;
            const bool gate = (bn >= HID);
#pragma unroll
            for (int mi = 0; mi < 2; mi++) {
                const int row0 = bm + m_off + mi * 16 + group;
#pragma unroll
                for (int ni = 0; ni < 8; ni++) {
                    const int col = bn + n_off + ni * 8 + tid4 * 2;
                    float u0 = acc[mi][ni][0], u1 = acc[mi][ni][1];
                    float u2 = acc[mi][ni][2], u3 = acc[mi][ni][3];
                    if (gate) {
                        const float bz0 = __ldg(&bias[col - HID]);
                        const float bz1 = __ldg(&bias[col + 1 - HID]);
                        u0 = __fdividef(1.0f, 1.0f + __expf(-(u0 + bz0)));
                        u1 = __fdividef(1.0f, 1.0f + __expf(-(u1 + bz1)));
                        u2 = __fdividef(1.0f, 1.0f + __expf(-(u2 + bz0)));
                        u3 = __fdividef(1.0f, 1.0f + __expf(-(u3 + bz1)));
                    }
                    *reinterpret_cast<__half2*>(&U[(size_t)row0 * NCOLS + col]) =
                        __floats2half2_rn(u0, u1);
                    *reinterpret_cast<__half2*>(&U[(size_t)(row0 + 8) * NCOLS + col]) =
                        __floats2half2_rn(u2, u3);
                    acc[mi][ni][0] = 0.f; acc[mi][ni][1] = 0.f;
                    acc[mi][ni][2] = 0.f; acc[mi][ni][3] = 0.f;
                }
            }
        }
    }
}

// ============================================================
// Chunked parallel scan, half2 lanes, 64 chunks (separate pass2 —
// the fused-prologue variant regressed in R14; structure protected).
// ============================================================
__global__ void __launch_bounds__(256)
scan_pass1(const __half* __restrict__ U, float* __restrict__ P, float* __restrict__ S) {
    int gid   = blockIdx.x * blockDim.x + threadIdx.x;   // 0 .. NCH*BH2-1
    int lane2 = gid & (BH2 - 1);
    int kc    = gid >> 12;                               // BH2 = 4096
    int b  = lane2 >> 8;                                 // HID/2 = 256
    int h2 = lane2 & 255;
    int l0 = kc * CHL;
    const __half2* U2 = reinterpret_cast<const __half2*>(U);

    float c0 = 0.f, c1 = 0.f, p0 = 1.f, p1 = 1.f;
    for (int l = l0; l < l0 + CHL; l += SUNROLL) {
        float2 f[SUNROLL], xt[SUNROLL];
#pragma unroll
        for (int u = 0; u < SUNROLL; u++) {
            size_t base = ((size_t)(l + u) * BATCH + b) * (NCOLS / 2) + h2;
            xt[u] = __half22float2(U2[base]);
            f [u] = __half22float2(U2[base + HID / 2]);
        }
#pragma unroll
        for (int u = 0; u < SUNROLL; u++) {
            c0 = fmaf(f[u].x, c0 - xt[u].x, xt[u].x);
            c1 = fmaf(f[u].y, c1 - xt[u].y, xt[u].y);
            p0 *= f[u].x;
            p1 *= f[u].y;
        }
    }
    size_t o2 = (size_t)kc * BH2 + lane2;
    reinterpret_cast<float2*>(P)[o2] = make_float2(p0, p1);
    reinterpret_cast<float2*>(S)[o2] = make_float2(c0, c1);
}

__global__ void __launch_bounds__(128)
scan_pass2(const float* __restrict__ P, const float* __restrict__ S,
           float* __restrict__ Cin) {
    int lane = blockIdx.x * blockDim.x + threadIdx.x;   // 0..BH-1
    float c = 0.f;
#pragma unroll
    for (int k = 0; k < NCH; k++) {
        Cin[(size_t)k * BH + lane] = c;
        c = fmaf(P[(size_t)k * BH + lane], c, S[(size_t)k * BH + lane]);
    }
}

__global__ void __launch_bounds__(256)
scan_pass3(const __half* __restrict__ U, const __half* __restrict__ xin,
           const float* __restrict__ Cin, __half* __restrict__ hout) {
    int gid   = blockIdx.x * blockDim.x + threadIdx.x;
    int lane2 = gid & (BH2 - 1);
    int kc    = gid >> 12;
    int b  = lane2 >> 8;
    int h2 = lane2 & 255;
    int l0 = kc * CHL;
    const __half2* U2 = reinterpret_cast<const __half2*>(U);
    const __half2* X2 = reinterpret_cast<const __half2*>(xin);
    __half2* H2 = reinterpret_cast<__half2*>(hout);

    float2 cin = reinterpret_cast<const float2*>(Cin)[(size_t)kc * BH2 + lane2];
    float c0 = cin.x, c1 = cin.y;
    for (int l = l0; l < l0 + CHL; l += SUNROLL) {
        float2 f[SUNROLL], xt[SUNROLL], r[SUNROLL], xv[SUNROLL];
#pragma unroll
        for (int u = 0; u < SUNROLL; u++) {
            size_t row  = (size_t)(l + u) * BATCH + b;
            size_t base = row * (NCOLS / 2) + h2;
            xt[u] = __half22float2(U2[base]);
            f [u] = __half22float2(U2[base + HID / 2]);
            r [u] = __half22float2(U2[base + HID]);
            xv[u] = __half22float2(X2[row * (HID / 2) + h2]);
        }
#pragma unroll
        for (int u = 0; u < SUNROLL; u++) {
            c0 = fmaf(f[u].x, c0 - xt[u].x, xt[u].x);
            c1 = fmaf(f[u].y, c1 - xt[u].y, xt[u].y);
            float h0 = fmaf(r[u].x, c0 - xv[u].x, xv[u].x);
            float h1 = fmaf(r[u].y, c1 - xv[u].y, xv[u].y);
            size_t row = (size_t)(l + u) * BATCH + b;
            H2[row * (HID / 2) + h2] = __floats2half2_rn(h0, h1);
        }
    }
}

// ============================================================
// Final FC: 4 rows per warp (1024 blocks; fc_W staging 20 MB).
// ============================================================
#define FC_RPW 4
__global__ void __launch_bounds__(256)
fc_kernel(const __half* __restrict__ Hf, const float* __restrict__ fcW,
          const float* __restrict__ fcb, float* __restrict__ out) {
    __shared__ float Wsm[OUT_F * HID];
    int tid = threadIdx.x;
    for (int i = tid; i < OUT_F * HID; i += 256) Wsm[i] = fcW[i];
    __syncthreads();

    int warp = tid >> 5, lane = tid & 31;
    int row0 = (blockIdx.x * 8 + warp) * FC_RPW;

#pragma unroll
    for (int rr = 0; rr < FC_RPW; rr++) {
        int row = row0 + rr;
        const __half2* hp = reinterpret_cast<const __half2*>(Hf + (size_t)row * HID);

        float acc[OUT_F];
#pragma unroll
        for (int n = 0; n < OUT_F; n++) acc[n] = 0.f;

        for (int k2 = lane; k2 < HID / 2; k2 += 32) {
            float2 xv = __half22float2(hp[k2]);
#pragma unroll
            for (int n = 0; n < OUT_F; n++) {
                acc[n] = fmaf(xv.x, Wsm[n * HID + 2 * k2],     acc[n]);
                acc[n] = fmaf(xv.y, Wsm[n * HID + 2 * k2 + 1], acc[n]);
            }
        }
#pragma unroll
        for (int n = 0; n < OUT_F; n++) {
            float v = acc[n];
            v += __shfl_xor_sync(0xFFFFFFFFu, v, 16);
            v += __shfl_xor_sync(0xFFFFFFFFu, v, 8);
            v += __shfl_xor_sync(0xFFFFFFFFu, v, 4);
            v += __shfl_xor_sync(0xFFFFFFFFu, v, 2);
            v += __shfl_xor_sync(0xFFFFFFFFu, v, 1);
            if (lane == 0) out[(size_t)row * OUT_F + n] = v + fcb[n];
        }
    }
}

// ============================================================
// Host launcher (graph-capturable: kernel launches only)
// ============================================================
extern "C" void kernel_launch(void* const* d_in, const int* in_sizes, int n_in,
                              void* d_out, int out_size) {
    const float* x    = (const float*)d_in[0];
    const float* Ws   = (const float*)d_in[1];
    const float* bs   = (const float*)d_in[2];
    const float* fcW  = (const float*)d_in[3];
    const float* fcb  = (const float*)d_in[4];
    float* out        = (float*)d_out;

    float *P, *S, *Cin;
    __half *U, *A0, *A1, *Wh;
    cudaGetSymbolAddress((void**)&U,   g_U);
    cudaGetSymbolAddress((void**)&A0,  g_A0);
    cudaGetSymbolAddress((void**)&A1,  g_A1);
    cudaGetSymbolAddress((void**)&Wh,  g_Wh);
    cudaGetSymbolAddress((void**)&P,   g_P);
    cudaGetSymbolAddress((void**)&S,   g_S);
    cudaGetSymbolAddress((void**)&Cin, g_Cin);

    cudaFuncSetAttribute(sru_gemm_mma,
                         cudaFuncAttributeMaxDynamicSharedMemorySize, SMEM_GEMM);

    const int nA4   = MROWS * HID / 4;
    const int nWall = NLAY * NCOLS * HID / 4;
    const int scan_grid = NCH * BH2 / 256;    // 1024

    // One-time: convert all weights and layer-0 activations to fp16.
    convert_fp16<<<(nWall + 255) / 256, 256>>>(Ws, Wh, nWall);
    convert_fp16<<<(nA4 + 255) / 256, 256>>>(x, A0, nA4);

    __half* cur = A0;
    __half* nxt = A1;
    for (int l = 0; l < NLAY; l++) {
        const size_t woff = (size_t)l * NCOLS * HID;
        sru_gemm_mma<<<GPERS, 512, SMEM_GEMM>>>(cur, Wh + woff,
                                                bs + (size_t)l * (2 * HID), U);
        scan_pass1<<<scan_grid, 256>>>(U, P, S);
        scan_pass2<<<BH / 128, 128>>>(P, S, Cin);
        scan_pass3<<<scan_grid, 256>>>(U, cur, Cin, nxt);
        __half* t = cur; cur = nxt; nxt = t;
    }
    fc_kernel<<<MROWS / (8 * FC_RPW), 256>>>(cur, fcW, fcb, out);
}